// round 4
// baseline (speedup 1.0000x reference)
#include <cuda_runtime.h>

// Pair_83811991814342
// in:  (1, 1024, 260) fp32; only first 512 rows used
// out: (1, 512*512, 522) fp32 : [x[i](260) | x[j](260) | r1 | r2]

#define NROWS 512
#define DIM   260
#define HD    130            // float2 per input row
#define HC    261            // float2 per output row (522/2)
#define TI    8
#define TJ    8
#define NT    288

__global__ __launch_bounds__(NT)
void pair_kernel(const float* __restrict__ in, float* __restrict__ out) {
    const int bi = blockIdx.y * TI;
    const int bj = blockIdx.x * TJ;
    const int c  = threadIdx.x;         // float2 column in output row

    if (c < 2 * HD) {
        // ---- Data columns: pure broadcast path ----
        const bool lo = (c < HD);
        const float2* src = reinterpret_cast<const float2*>(in)
                          + (lo ? (bi * HD + c) : (bj * HD + (c - HD)));
        float2 v[8];
        #pragma unroll
        for (int r = 0; r < 8; r++) v[r] = __ldg(&src[r * HD]);

        float2* ob = reinterpret_cast<float2*>(out)
                   + (size_t)(bi * NROWS + bj) * HC + c;
        #pragma unroll
        for (int il = 0; il < TI; il++) {
            #pragma unroll
            for (int jl = 0; jl < TJ; jl++) {
                __stcs(&ob[(size_t)(il * NROWS + jl) * HC], lo ? v[il] : v[jl]);
            }
        }
    } else if (c == 2 * HD) {
        // ---- Single thread per block: compute + store all 64 (r1, r2) pairs ----
        float x1i[TI], y1i[TI], x2i[TI], y2i[TI], ai[TI];
        float x1j[TJ], y1j[TJ], x2j[TJ], y2j[TJ], aj[TJ];
        #pragma unroll
        for (int r = 0; r < TI; r++) {
            const float4 b = __ldg(reinterpret_cast<const float4*>(
                in + (bi + r) * DIM + (DIM - 4)));
            x1i[r] = b.x; y1i[r] = b.y; x2i[r] = b.z; y2i[r] = b.w;
            ai[r] = (b.z - b.x) * (b.w - b.y);
        }
        #pragma unroll
        for (int r = 0; r < TJ; r++) {
            const float4 b = __ldg(reinterpret_cast<const float4*>(
                in + (bj + r) * DIM + (DIM - 4)));
            x1j[r] = b.x; y1j[r] = b.y; x2j[r] = b.z; y2j[r] = b.w;
            aj[r] = (b.z - b.x) * (b.w - b.y);
        }
        float2* ob = reinterpret_cast<float2*>(out)
                   + (size_t)(bi * NROWS + bj) * HC + 2 * HD;
        #pragma unroll
        for (int il = 0; il < TI; il++) {
            #pragma unroll
            for (int jl = 0; jl < TJ; jl++) {
                float w = fmaxf(0.0f, fminf(x2i[il], x2j[jl]) - fmaxf(x1i[il], x1j[jl]));
                float h = fmaxf(0.0f, fminf(y2i[il], y2j[jl]) - fmaxf(y1i[il], y1j[jl]));
                float inter = w * h;
                __stcs(&ob[(size_t)(il * NROWS + jl) * HC],
                       make_float2(inter / ai[il], inter / aj[jl]));
            }
        }
    }
}

extern "C" void kernel_launch(void* const* d_in, const int* in_sizes, int n_in,
                              void* d_out, int out_size) {
    const float* in = (const float*)d_in[0];
    float* out = (float*)d_out;
    dim3 grid(NROWS / TJ, NROWS / TI);  // 64 x 64 blocks
    pair_kernel<<<grid, NT>>>(in, out);
}